// round 10
// baseline (speedup 1.0000x reference)
#include <cuda_runtime.h>
#include <cuda_fp16.h>
#include <cuda_bf16.h>
#include <cstdint>

// Problem constants
#define NN 100000
#define EE 1600000
#define DD 128
#define NB_SCAN ((NN + 255) / 256)   // 391 scan blocks

// ---------------- device scratch (no allocations allowed) ----------------
// NOTE: g_deg and g_done are zero on first use (CUDA zero-init) and re-zeroed
// by k_scan_final on every call, keeping kernel_launch deterministic.
__device__ int    g_done;
__device__ int    g_deg[NN];
__device__ int    g_rowptr[NN + 1];
__device__ int    g_pos[EE];         // rank of edge within its dst row
__device__ int    g_psum[NB_SCAN];
__device__ int2   g_edge[EE];        // (col, wgt-as-int-bits)
__device__ float  g_dinv[NN];
__device__ __half g_h1[NN * DD];     // GEMM1 output
__device__ __half g_h2[NN * DD];     // fused agg+GEMM2 output

// ---------------- helpers ----------------
__device__ __forceinline__ int load_idx(const void* ei, int pos, int is64) {
    if (is64) return (int)((const long long*)ei)[pos];
    return ((const int*)ei)[pos];
}

// per-block dtype detect: int64 node ids (<2^31) have zero hi-words at every
// odd int32 position. Uniform result; ~64 L2-hit loads per block.
__device__ __forceinline__ int detect_is64(const int* ei32) {
    __shared__ int s_is64;
    if (threadIdx.x == 0) {
        int zeros = 0;
#pragma unroll
        for (int j = 0; j < 64; j++)
            if (ei32[2 * j + 1] == 0) zeros++;
        s_is64 = (zeros >= 60) ? 1 : 0;
    }
    __syncthreads();
    return s_is64;
}

// ---------------- graph-build kernels ----------------

// count degrees; atomicAdd return value = edge's rank within its dst row.
__global__ void k_count(const void* __restrict__ ei, int E) {
    int is64 = detect_is64((const int*)ei);
    int i = blockIdx.x * blockDim.x + threadIdx.x;
    if (!is64 && (E & 3) == 0) {
        int base = 4 * i;
        if (base >= E) return;
        const int4* dst4 = (const int4*)((const int*)ei + E);
        int4 d = dst4[i];
        int4 p = make_int4(0, 0, 0, 0);
        if ((unsigned)d.x < (unsigned)NN) p.x = atomicAdd(&g_deg[d.x], 1);
        if ((unsigned)d.y < (unsigned)NN) p.y = atomicAdd(&g_deg[d.y], 1);
        if ((unsigned)d.z < (unsigned)NN) p.z = atomicAdd(&g_deg[d.z], 1);
        if ((unsigned)d.w < (unsigned)NN) p.w = atomicAdd(&g_deg[d.w], 1);
        ((int4*)g_pos)[i] = p;
    } else {
        if (i >= E) return;
        int d = load_idx(ei, E + i, is64);
        int p = 0;
        if ((unsigned)d < (unsigned)NN) p = atomicAdd(&g_deg[d], 1);
        g_pos[i] = p;
    }
}

// Per-block sums of deg -> g_psum[b]; LAST block scans g_psum (exclusive).
__global__ void k_reduce() {
    __shared__ int ws[8];
    __shared__ int s_last;
    int b = blockIdx.x, t = threadIdx.x;
    int lane = t & 31, w = t >> 5;
    int i = b * 256 + t;
    int v = (i < NN) ? g_deg[i] : 0;
#pragma unroll
    for (int off = 16; off > 0; off >>= 1)
        v += __shfl_xor_sync(0xFFFFFFFFu, v, off);
    if (lane == 0) ws[w] = v;
    __syncthreads();
    if (t == 0) {
        int s = 0;
#pragma unroll
        for (int k = 0; k < 8; k++) s += ws[k];
        g_psum[b] = s;
        __threadfence();
        int done = atomicAdd(&g_done, 1);
        s_last = (done == gridDim.x - 1) ? 1 : 0;
    }
    __syncthreads();
    if (!s_last) return;

    __shared__ int wsum[8];
    __shared__ int carry;
    if (t == 0) carry = 0;
    __syncthreads();
    for (int base = 0; base < NB_SCAN; base += 256) {
        int x = (base + t < NB_SCAN) ? g_psum[base + t] : 0;
        int s = x;
#pragma unroll
        for (int off = 1; off < 32; off <<= 1) {
            int u = __shfl_up_sync(0xFFFFFFFFu, s, off);
            if (lane >= off) s += u;
        }
        if (lane == 31) wsum[w] = s;
        __syncthreads();
        if (w == 0 && lane < 8) {
            int y = wsum[lane];
#pragma unroll
            for (int off = 1; off < 8; off <<= 1) {
                int u = __shfl_up_sync(0xFFu, y, off);
                if (lane >= off) y += u;
            }
            wsum[lane] = y;
        }
        __syncthreads();
        int pre = (w > 0) ? wsum[w - 1] : 0;
        int c = carry;
        if (base + t < NB_SCAN) g_psum[base + t] = c + pre + s - x;  // exclusive
        __syncthreads();
        if (t == 0) carry = c + wsum[7];
        __syncthreads();
    }
}

// Block-local inclusive scan + psum offset -> rowptr; dinv fused.
// Also re-zeroes g_deg and g_done for the next call (determinism invariant).
__global__ void k_scan_final() {
    __shared__ int wsum[8];
    int b = blockIdx.x, t = threadIdx.x;
    int lane = t & 31, w = t >> 5;
    int i = b * 256 + t;
    int v = 0;
    if (i < NN) {
        v = g_deg[i];
        g_dinv[i] = rsqrtf((float)v + 1.0f);
        g_deg[i] = 0;
    }
    if (b == 0 && t == 0) g_done = 0;
    int s = v;
#pragma unroll
    for (int off = 1; off < 32; off <<= 1) {
        int u = __shfl_up_sync(0xFFFFFFFFu, s, off);
        if (lane >= off) s += u;
    }
    if (lane == 31) wsum[w] = s;
    __syncthreads();
    if (w == 0 && lane < 8) {
        int ws = wsum[lane];
#pragma unroll
        for (int off = 1; off < 8; off <<= 1) {
            int u = __shfl_up_sync(0xFFu, ws, off);
            if (lane >= off) ws += u;
        }
        wsum[lane] = ws;
    }
    __syncthreads();
    int pre = (w > 0) ? wsum[w - 1] : 0;
    int base = g_psum[b];
    if (i < NN) g_rowptr[i + 1] = base + pre + s;
    if (b == 0 && t == 0) g_rowptr[0] = 0;
}

// atomic-free scatter: idx = rowptr[d] + pos[i]
__device__ __forceinline__ void scatter_one(int s, int d, int p) {
    if ((unsigned)s >= (unsigned)NN || (unsigned)d >= (unsigned)NN) return;
    int idx = g_rowptr[d] + p;
    float w = g_dinv[s] * g_dinv[d];
    g_edge[idx] = make_int2(s, __float_as_int(w));
}

__global__ void k_scatter(const void* __restrict__ ei, int E) {
    int is64 = detect_is64((const int*)ei);
    int i = blockIdx.x * blockDim.x + threadIdx.x;
    if (!is64 && (E & 3) == 0) {
        int base = 4 * i;
        if (base >= E) return;
        const int4* src4 = (const int4*)((const int*)ei);
        const int4* dst4 = (const int4*)((const int*)ei + E);
        int4 s = src4[i];
        int4 d = dst4[i];
        int4 p = ((const int4*)g_pos)[i];
        scatter_one(s.x, d.x, p.x);
        scatter_one(s.y, d.y, p.y);
        scatter_one(s.z, d.z, p.z);
        scatter_one(s.w, d.w, p.w);
    } else {
        if (i >= E) return;
        int s = load_idx(ei, i, is64);
        int d = load_idx(ei, E + i, is64);
        scatter_one(s, d, g_pos[i]);
    }
}

// ---------------- shared device routines ----------------
#define SRS 136  // smem row stride in halves

// Aggregate one node's row (fp16 gathers, fp32 acc): returns 4 floats for
// this lane's columns [4*lane, 4*lane+4).
__device__ __forceinline__ void agg_row(const uint2* __restrict__ hin, int node,
                                        int lane, float& ax, float& ay,
                                        float& az, float& aw) {
    int s = g_rowptr[node];
    int e = g_rowptr[node + 1];
    float di = g_dinv[node];
    float sw = di * di;
    {
        uint2 u = hin[node * 32 + lane];
        float2 f0 = __half22float2(*reinterpret_cast<__half2*>(&u.x));
        float2 f1 = __half22float2(*reinterpret_cast<__half2*>(&u.y));
        ax = f0.x * sw; ay = f0.y * sw; az = f1.x * sw; aw = f1.y * sw;
    }
    int j = s;
    for (; j + 3 < e; j += 4) {
        int2 e0 = g_edge[j],     e1 = g_edge[j + 1];
        int2 e2 = g_edge[j + 2], e3 = g_edge[j + 3];
        uint2 u0 = hin[e0.x * 32 + lane];
        uint2 u1 = hin[e1.x * 32 + lane];
        uint2 u2 = hin[e2.x * 32 + lane];
        uint2 u3 = hin[e3.x * 32 + lane];
        float w0 = __int_as_float(e0.y), w1 = __int_as_float(e1.y);
        float w2 = __int_as_float(e2.y), w3 = __int_as_float(e3.y);
        float2 p0 = __half22float2(*reinterpret_cast<__half2*>(&u0.x));
        float2 p1 = __half22float2(*reinterpret_cast<__half2*>(&u0.y));
        float2 q0 = __half22float2(*reinterpret_cast<__half2*>(&u1.x));
        float2 q1 = __half22float2(*reinterpret_cast<__half2*>(&u1.y));
        float2 r0 = __half22float2(*reinterpret_cast<__half2*>(&u2.x));
        float2 r1 = __half22float2(*reinterpret_cast<__half2*>(&u2.y));
        float2 t0 = __half22float2(*reinterpret_cast<__half2*>(&u3.x));
        float2 t1 = __half22float2(*reinterpret_cast<__half2*>(&u3.y));
        ax += p0.x * w0 + q0.x * w1 + r0.x * w2 + t0.x * w3;
        ay += p0.y * w0 + q0.y * w1 + r0.y * w2 + t0.y * w3;
        az += p1.x * w0 + q1.x * w1 + r1.x * w2 + t1.x * w3;
        aw += p1.y * w0 + q1.y * w1 + r1.y * w2 + t1.y * w3;
    }
    for (; j < e; j++) {
        int2 e0 = g_edge[j];
        float w0 = __int_as_float(e0.y);
        uint2 u0 = hin[e0.x * 32 + lane];
        float2 p0 = __half22float2(*reinterpret_cast<__half2*>(&u0.x));
        float2 p1 = __half22float2(*reinterpret_cast<__half2*>(&u0.y));
        ax += p0.x * w0;
        ay += p0.y * w0;
        az += p1.x * w0;
        aw += p1.y * w0;
    }
}

// HMMA mainloop over staged sA/sBT -> fp16 out rows [row0, row0+128)
__device__ __forceinline__ void gemm_tile(const __half* sA, const __half* sBT,
                                          __half* __restrict__ out, int row0,
                                          int n, int tid) {
    int lane = tid & 31, warp = tid >> 5;
    int g = lane >> 2, tg = lane & 3;
    int rb = warp * 16;

    float acc[16][4];
#pragma unroll
    for (int nt = 0; nt < 16; nt++)
#pragma unroll
        for (int q = 0; q < 4; q++) acc[nt][q] = 0.f;

#pragma unroll
    for (int ks = 0; ks < 8; ks++) {
        int k0 = ks * 16;
        uint32_t a0 = *(const uint32_t*)(sA + (rb + g) * SRS + k0 + tg * 2);
        uint32_t a1 = *(const uint32_t*)(sA + (rb + g + 8) * SRS + k0 + tg * 2);
        uint32_t a2 = *(const uint32_t*)(sA + (rb + g) * SRS + k0 + 8 + tg * 2);
        uint32_t a3 = *(const uint32_t*)(sA + (rb + g + 8) * SRS + k0 + 8 + tg * 2);
#pragma unroll
        for (int nt = 0; nt < 16; nt++) {
            uint32_t b0 = *(const uint32_t*)(sBT + (nt * 8 + g) * SRS + k0 + tg * 2);
            uint32_t b1 = *(const uint32_t*)(sBT + (nt * 8 + g) * SRS + k0 + 8 + tg * 2);
            asm volatile(
                "mma.sync.aligned.m16n8k16.row.col.f32.f16.f16.f32 "
                "{%0,%1,%2,%3},{%4,%5,%6,%7},{%8,%9},{%0,%1,%2,%3};"
                : "+f"(acc[nt][0]), "+f"(acc[nt][1]),
                  "+f"(acc[nt][2]), "+f"(acc[nt][3])
                : "r"(a0), "r"(a1), "r"(a2), "r"(a3), "r"(b0), "r"(b1));
        }
    }

    int r1 = row0 + rb + g;
    int r2 = r1 + 8;
#pragma unroll
    for (int nt = 0; nt < 16; nt++) {
        int c = nt * 8 + tg * 2;
        if (r1 < n) {
            __half2 h = __floats2half2_rn(acc[nt][0], acc[nt][1]);
            *(__half2*)(out + r1 * 128 + c) = h;
        }
        if (r2 < n) {
            __half2 h = __floats2half2_rn(acc[nt][2], acc[nt][3]);
            *(__half2*)(out + r2 * 128 + c) = h;
        }
    }
}

// stage W^T as fp16: W row-major [k][n] -> sBT[n][k]
__device__ __forceinline__ void stage_wt(const float* __restrict__ Wm,
                                         __half* sBT, int tid) {
#pragma unroll
    for (int i = 0; i < 64; i++) {
        int idx = tid + 256 * i;
        int k = idx >> 7, nn = idx & 127;
        sBT[nn * SRS + k] = __float2half(Wm[idx]);
    }
}

// ---------------- kernels: gemm1, fused agg+gemm2, agg2 ----------------

// gemm1: h1 = x@W1 (fp32 in, fp16 out)
__global__ void k_gemm1(const float* __restrict__ Ain, const float* __restrict__ Wm,
                        __half* __restrict__ out, int n) {
    extern __shared__ __half smh[];
    __half* sA = smh;
    __half* sBT = smh + 128 * SRS;
    int tid = threadIdx.x;
    int row0 = blockIdx.x * 128;

    stage_wt(Wm, sBT, tid);
    const float4* A4 = (const float4*)Ain;
#pragma unroll
    for (int i = 0; i < 16; i++) {
        int idx = tid + 256 * i;
        int r = idx >> 5, c = (idx & 31) * 4;
        float4 v = make_float4(0.f, 0.f, 0.f, 0.f);
        if (row0 + r < n) v = A4[(row0 + r) * 32 + (idx & 31)];
        __half2 h0 = __floats2half2_rn(v.x, v.y);
        __half2 h1 = __floats2half2_rn(v.z, v.w);
        *(__half2*)(sA + r * SRS + c) = h0;
        *(__half2*)(sA + r * SRS + c + 2) = h1;
    }
    __syncthreads();
    gemm_tile(sA, sBT, out, row0, n, tid);
}

// fused: a1 = relu(agg(h1)+b1) (to smem, fp16) ; h2 = a1@W2 (fp16, SEPARATE buf)
__global__ void k_agg_gemm(const uint2* __restrict__ hin, const float* __restrict__ Wm,
                           const float* __restrict__ bias, __half* __restrict__ out,
                           int n) {
    extern __shared__ __half smh[];
    __half* sA = smh;
    __half* sBT = smh + 128 * SRS;
    int tid = threadIdx.x;
    int lane = tid & 31, warp = tid >> 5;
    int row0 = blockIdx.x * 128;

    stage_wt(Wm, sBT, tid);

    float4 bv = ((const float4*)bias)[lane];
#pragma unroll
    for (int rr = 0; rr < 16; rr++) {
        int r = warp * 16 + rr;
        int node = row0 + r;
        float ax = 0.f, ay = 0.f, az = 0.f, aw = 0.f;
        if (node < n) {
            agg_row(hin, node, lane, ax, ay, az, aw);
            ax = fmaxf(ax + bv.x, 0.f);
            ay = fmaxf(ay + bv.y, 0.f);
            az = fmaxf(az + bv.z, 0.f);
            aw = fmaxf(aw + bv.w, 0.f);
        }
        __half2 h0 = __floats2half2_rn(ax, ay);
        __half2 h1 = __floats2half2_rn(az, aw);
        *(__half2*)(sA + r * SRS + lane * 4) = h0;
        *(__half2*)(sA + r * SRS + lane * 4 + 2) = h1;
    }
    __syncthreads();
    gemm_tile(sA, sBT, out, row0, n, tid);
}

// agg2: out = LN(agg(h2)+b2) (fp32 out), warp per node
__global__ void k_agg_ln(const uint2* __restrict__ hin, float* __restrict__ outp,
                         const float* __restrict__ bias, const float* __restrict__ gamma,
                         const float* __restrict__ beta) {
    int gw = (blockIdx.x * blockDim.x + threadIdx.x) >> 5;
    int lane = threadIdx.x & 31;
    if (gw >= NN) return;
    float ax, ay, az, aw;
    agg_row(hin, gw, lane, ax, ay, az, aw);

    float4 bv = ((const float4*)bias)[lane];
    ax += bv.x; ay += bv.y; az += bv.z; aw += bv.w;

    float sum = ax + ay + az + aw;
#pragma unroll
    for (int off = 16; off > 0; off >>= 1)
        sum += __shfl_xor_sync(0xFFFFFFFFu, sum, off);
    float mu = sum * (1.0f / 128.0f);
    float dx = ax - mu, dy = ay - mu, dz = az - mu, dw = aw - mu;
    float sq = dx * dx + dy * dy + dz * dz + dw * dw;
#pragma unroll
    for (int off = 16; off > 0; off >>= 1)
        sq += __shfl_xor_sync(0xFFFFFFFFu, sq, off);
    float rstd = rsqrtf(sq * (1.0f / 128.0f) + 1e-5f);
    float4 gv = ((const float4*)gamma)[lane];
    float4 btv = ((const float4*)beta)[lane];
    float4 o;
    o.x = dx * rstd * gv.x + btv.x;
    o.y = dy * rstd * gv.y + btv.y;
    o.z = dz * rstd * gv.z + btv.z;
    o.w = dw * rstd * gv.w + btv.w;
    ((float4*)outp)[gw * 32 + lane] = o;
}

// ---------------- launch ----------------
extern "C" void kernel_launch(void* const* d_in, const int* in_sizes, int n_in,
                              void* d_out, int out_size) {
    const float* x   = (const float*)d_in[0];
    const void*  ei  = d_in[1];
    const float* W1  = (const float*)d_in[2];
    const float* b1  = (const float*)d_in[3];
    const float* W2  = (const float*)d_in[4];
    const float* b2  = (const float*)d_in[5];
    const float* gm  = (const float*)d_in[6];
    const float* bt  = (const float*)d_in[7];
    float*       out = (float*)d_out;

    int E = in_sizes[1] / 2;

    __half* h1buf; cudaGetSymbolAddress((void**)&h1buf, g_h1);
    __half* h2buf; cudaGetSymbolAddress((void**)&h2buf, g_h2);

    const size_t smem_gemm = 2 * 128 * SRS * sizeof(__half);  // 69632 B
    static bool s_init_done = false;
    static cudaStream_t s_side = nullptr;
    static cudaEvent_t ev_fork = nullptr, ev_join = nullptr;
    if (!s_init_done) {
        cudaFuncSetAttribute(k_gemm1,
                             cudaFuncAttributeMaxDynamicSharedMemorySize, (int)smem_gemm);
        cudaFuncSetAttribute(k_agg_gemm,
                             cudaFuncAttributeMaxDynamicSharedMemorySize, (int)smem_gemm);
        cudaStreamCreateWithFlags(&s_side, cudaStreamNonBlocking);
        cudaEventCreateWithFlags(&ev_fork, cudaEventDisableTiming);
        cudaEventCreateWithFlags(&ev_join, cudaEventDisableTiming);
        s_init_done = true;
    }

    int ebl4 = (E / 4 + 255) / 256;
    int ebl = (E + 255) / 256;
    int cnt_blocks = ((E & 3) == 0) ? ebl4 : ebl;
    int agg_blocks = (NN * 32 + 255) / 256;
    int gemm_blocks = (NN + 127) / 128;

    // ---- fork: gemm1 = x@W1 on side stream (graph-independent) ----
    cudaEventRecord(ev_fork, 0);
    cudaStreamWaitEvent(s_side, ev_fork, 0);
    k_gemm1<<<gemm_blocks, 256, smem_gemm, s_side>>>(x, W1, h1buf, NN);
    cudaEventRecord(ev_join, s_side);

    // ---- CSR build on main stream (deg/done pre-zeroed invariant) ----
    k_count<<<cnt_blocks, 256>>>(ei, E);
    k_reduce<<<NB_SCAN, 256>>>();
    k_scan_final<<<NB_SCAN, 256>>>();
    k_scatter<<<cnt_blocks, 256>>>(ei, E);

    // ---- join gemm1, then fused agg1+gemm2: h1 -> h2 (separate buffer) ----
    cudaStreamWaitEvent(0, ev_join, 0);
    k_agg_gemm<<<gemm_blocks, 256, smem_gemm>>>((const uint2*)h1buf, W2, b1, h2buf, NN);

    // ---- agg2 + LayerNorm -> out ----
    k_agg_ln<<<agg_blocks, 256>>>((const uint2*)h2buf, out, b2, gm, bt);
}

// round 11
// speedup vs baseline: 1.0909x; 1.0909x over previous
#include <cuda_runtime.h>
#include <cuda_fp16.h>
#include <cuda_bf16.h>
#include <cstdint>

// Problem constants
#define NN 100000
#define EE 1600000
#define DD 128
#define NB_SCAN ((NN + 255) / 256)   // 391 scan blocks
#define NHALF 50048                  // 391 * 128, gemm-tile-aligned split

// ---------------- device scratch (no allocations allowed) ----------------
// g_deg/g_done zero on first use (CUDA zero-init), re-zeroed by k_scan_final.
__device__ int    g_done;
__device__ int    g_deg[NN];
__device__ int    g_rowptr[NN + 1];
__device__ int    g_pos[EE];
__device__ int    g_psum[NB_SCAN];
__device__ int2   g_edge[EE];        // (col, wgt-as-int-bits)
__device__ float  g_dinv[NN];
__device__ __half g_h1[NN * DD];     // GEMM1 output
__device__ __half g_a1[NN * DD];     // layer-1 activation
__device__ __half g_h2[NN * DD];     // GEMM2 output

// ---------------- helpers ----------------
__device__ __forceinline__ int load_idx(const void* ei, int pos, int is64) {
    if (is64) return (int)((const long long*)ei)[pos];
    return ((const int*)ei)[pos];
}

__device__ __forceinline__ int detect_is64(const int* ei32) {
    __shared__ int s_is64;
    if (threadIdx.x == 0) {
        int zeros = 0;
#pragma unroll
        for (int j = 0; j < 64; j++)
            if (ei32[2 * j + 1] == 0) zeros++;
        s_is64 = (zeros >= 60) ? 1 : 0;
    }
    __syncthreads();
    return s_is64;
}

// ---------------- graph-build kernels ----------------

__global__ void k_count(const void* __restrict__ ei, int E) {
    int is64 = detect_is64((const int*)ei);
    int i = blockIdx.x * blockDim.x + threadIdx.x;
    if (!is64 && (E & 3) == 0) {
        int base = 4 * i;
        if (base >= E) return;
        const int4* dst4 = (const int4*)((const int*)ei + E);
        int4 d = dst4[i];
        int4 p = make_int4(0, 0, 0, 0);
        if ((unsigned)d.x < (unsigned)NN) p.x = atomicAdd(&g_deg[d.x], 1);
        if ((unsigned)d.y < (unsigned)NN) p.y = atomicAdd(&g_deg[d.y], 1);
        if ((unsigned)d.z < (unsigned)NN) p.z = atomicAdd(&g_deg[d.z], 1);
        if ((unsigned)d.w < (unsigned)NN) p.w = atomicAdd(&g_deg[d.w], 1);
        ((int4*)g_pos)[i] = p;
    } else {
        if (i >= E) return;
        int d = load_idx(ei, E + i, is64);
        int p = 0;
        if ((unsigned)d < (unsigned)NN) p = atomicAdd(&g_deg[d], 1);
        g_pos[i] = p;
    }
}

// Per-block sums -> g_psum[b]; LAST block scans g_psum (exclusive).
__global__ void k_reduce() {
    __shared__ int ws[8];
    __shared__ int s_last;
    int b = blockIdx.x, t = threadIdx.x;
    int lane = t & 31, w = t >> 5;
    int i = b * 256 + t;
    int v = (i < NN) ? g_deg[i] : 0;
#pragma unroll
    for (int off = 16; off > 0; off >>= 1)
        v += __shfl_xor_sync(0xFFFFFFFFu, v, off);
    if (lane == 0) ws[w] = v;
    __syncthreads();
    if (t == 0) {
        int s = 0;
#pragma unroll
        for (int k = 0; k < 8; k++) s += ws[k];
        g_psum[b] = s;
        __threadfence();
        int done = atomicAdd(&g_done, 1);
        s_last = (done == gridDim.x - 1) ? 1 : 0;
    }
    __syncthreads();
    if (!s_last) return;

    __shared__ int wsum[8];
    __shared__ int carry;
    if (t == 0) carry = 0;
    __syncthreads();
    for (int base = 0; base < NB_SCAN; base += 256) {
        int x = (base + t < NB_SCAN) ? g_psum[base + t] : 0;
        int s = x;
#pragma unroll
        for (int off = 1; off < 32; off <<= 1) {
            int u = __shfl_up_sync(0xFFFFFFFFu, s, off);
            if (lane >= off) s += u;
        }
        if (lane == 31) wsum[w] = s;
        __syncthreads();
        if (w == 0 && lane < 8) {
            int y = wsum[lane];
#pragma unroll
            for (int off = 1; off < 8; off <<= 1) {
                int u = __shfl_up_sync(0xFFu, y, off);
                if (lane >= off) y += u;
            }
            wsum[lane] = y;
        }
        __syncthreads();
        int pre = (w > 0) ? wsum[w - 1] : 0;
        int c = carry;
        if (base + t < NB_SCAN) g_psum[base + t] = c + pre + s - x;
        __syncthreads();
        if (t == 0) carry = c + wsum[7];
        __syncthreads();
    }
}

// Block-local scan + psum offset -> rowptr; dinv fused; re-zero deg/done.
__global__ void k_scan_final() {
    __shared__ int wsum[8];
    int b = blockIdx.x, t = threadIdx.x;
    int lane = t & 31, w = t >> 5;
    int i = b * 256 + t;
    int v = 0;
    if (i < NN) {
        v = g_deg[i];
        g_dinv[i] = rsqrtf((float)v + 1.0f);
        g_deg[i] = 0;
    }
    if (b == 0 && t == 0) g_done = 0;
    int s = v;
#pragma unroll
    for (int off = 1; off < 32; off <<= 1) {
        int u = __shfl_up_sync(0xFFFFFFFFu, s, off);
        if (lane >= off) s += u;
    }
    if (lane == 31) wsum[w] = s;
    __syncthreads();
    if (w == 0 && lane < 8) {
        int ws = wsum[lane];
#pragma unroll
        for (int off = 1; off < 8; off <<= 1) {
            int u = __shfl_up_sync(0xFFu, ws, off);
            if (lane >= off) ws += u;
        }
        wsum[lane] = ws;
    }
    __syncthreads();
    int pre = (w > 0) ? wsum[w - 1] : 0;
    int base = g_psum[b];
    if (i < NN) g_rowptr[i + 1] = base + pre + s;
    if (b == 0 && t == 0) g_rowptr[0] = 0;
}

__device__ __forceinline__ void scatter_one(int s, int d, int p) {
    if ((unsigned)s >= (unsigned)NN || (unsigned)d >= (unsigned)NN) return;
    int idx = g_rowptr[d] + p;
    float w = g_dinv[s] * g_dinv[d];
    g_edge[idx] = make_int2(s, __float_as_int(w));
}

__global__ void k_scatter(const void* __restrict__ ei, int E) {
    int is64 = detect_is64((const int*)ei);
    int i = blockIdx.x * blockDim.x + threadIdx.x;
    if (!is64 && (E & 3) == 0) {
        int base = 4 * i;
        if (base >= E) return;
        const int4* src4 = (const int4*)((const int*)ei);
        const int4* dst4 = (const int4*)((const int*)ei + E);
        int4 s = src4[i];
        int4 d = dst4[i];
        int4 p = ((const int4*)g_pos)[i];
        scatter_one(s.x, d.x, p.x);
        scatter_one(s.y, d.y, p.y);
        scatter_one(s.z, d.z, p.z);
        scatter_one(s.w, d.w, p.w);
    } else {
        if (i >= E) return;
        int s = load_idx(ei, i, is64);
        int d = load_idx(ei, E + i, is64);
        scatter_one(s, d, g_pos[i]);
    }
}

// ---------------- tensor-core GEMM ----------------
#define SRS 136

__device__ __forceinline__ void stage_wt(const float* __restrict__ Wm,
                                         __half* sBT, int tid) {
#pragma unroll
    for (int i = 0; i < 64; i++) {
        int idx = tid + 256 * i;
        int k = idx >> 7, nn = idx & 127;
        sBT[nn * SRS + k] = __float2half(Wm[idx]);
    }
}

__device__ __forceinline__ void gemm_tile(const __half* sA, const __half* sBT,
                                          __half* __restrict__ out, int row0,
                                          int n, int tid) {
    int lane = tid & 31, warp = tid >> 5;
    int g = lane >> 2, tg = lane & 3;
    int rb = warp * 16;

    float acc[16][4];
#pragma unroll
    for (int nt = 0; nt < 16; nt++)
#pragma unroll
        for (int q = 0; q < 4; q++) acc[nt][q] = 0.f;

#pragma unroll
    for (int ks = 0; ks < 8; ks++) {
        int k0 = ks * 16;
        uint32_t a0 = *(const uint32_t*)(sA + (rb + g) * SRS + k0 + tg * 2);
        uint32_t a1 = *(const uint32_t*)(sA + (rb + g + 8) * SRS + k0 + tg * 2);
        uint32_t a2 = *(const uint32_t*)(sA + (rb + g) * SRS + k0 + 8 + tg * 2);
        uint32_t a3 = *(const uint32_t*)(sA + (rb + g + 8) * SRS + k0 + 8 + tg * 2);
#pragma unroll
        for (int nt = 0; nt < 16; nt++) {
            uint32_t b0 = *(const uint32_t*)(sBT + (nt * 8 + g) * SRS + k0 + tg * 2);
            uint32_t b1 = *(const uint32_t*)(sBT + (nt * 8 + g) * SRS + k0 + 8 + tg * 2);
            asm volatile(
                "mma.sync.aligned.m16n8k16.row.col.f32.f16.f16.f32 "
                "{%0,%1,%2,%3},{%4,%5,%6,%7},{%8,%9},{%0,%1,%2,%3};"
                : "+f"(acc[nt][0]), "+f"(acc[nt][1]),
                  "+f"(acc[nt][2]), "+f"(acc[nt][3])
                : "r"(a0), "r"(a1), "r"(a2), "r"(a3), "r"(b0), "r"(b1));
        }
    }

    int r1 = row0 + rb + g;
    int r2 = r1 + 8;
#pragma unroll
    for (int nt = 0; nt < 16; nt++) {
        int c = nt * 8 + tg * 2;
        if (r1 < n) {
            __half2 h = __floats2half2_rn(acc[nt][0], acc[nt][1]);
            *(__half2*)(out + r1 * 128 + c) = h;
        }
        if (r2 < n) {
            __half2 h = __floats2half2_rn(acc[nt][2], acc[nt][3]);
            *(__half2*)(out + r2 * 128 + c) = h;
        }
    }
}

// GEMM: out = A @ W, rows [row_base + 128*blockIdx, ...), limit n.
template <bool HALF_IN>
__global__ void k_gemm_tc(const void* __restrict__ Ain, const float* __restrict__ Wm,
                          __half* __restrict__ out, int row_base, int n) {
    extern __shared__ __half smh[];
    __half* sA = smh;
    __half* sBT = smh + 128 * SRS;
    int tid = threadIdx.x;
    int row0 = row_base + blockIdx.x * 128;

    stage_wt(Wm, sBT, tid);

    if (!HALF_IN) {
        const float4* A4 = (const float4*)Ain;
#pragma unroll
        for (int i = 0; i < 16; i++) {
            int idx = tid + 256 * i;
            int r = idx >> 5, c = (idx & 31) * 4;
            float4 v = make_float4(0.f, 0.f, 0.f, 0.f);
            if (row0 + r < n) v = A4[(row0 + r) * 32 + (idx & 31)];
            __half2 h0 = __floats2half2_rn(v.x, v.y);
            __half2 h1 = __floats2half2_rn(v.z, v.w);
            *(__half2*)(sA + r * SRS + c) = h0;
            *(__half2*)(sA + r * SRS + c + 2) = h1;
        }
    } else {
        const uint2* A2 = (const uint2*)Ain;
#pragma unroll
        for (int i = 0; i < 16; i++) {
            int idx = tid + 256 * i;
            int r = idx >> 5, c = (idx & 31) * 4;
            uint2 u = make_uint2(0u, 0u);
            if (row0 + r < n) u = A2[(row0 + r) * 32 + (idx & 31)];
            *(uint32_t*)(sA + r * SRS + c) = u.x;
            *(uint32_t*)(sA + r * SRS + c + 2) = u.y;
        }
    }
    __syncthreads();
    gemm_tile(sA, sBT, out, row0, n, tid);
}

// ---------------- aggregation: warp/node, half-warp per edge parity ----------
// Lane l: hw = l>>4 (edge parity), sl = l&15 (16-byte column block).
// Each lane: one LDG.128 per processed edge. Halves combined via shfl_xor(16).
// MODE 0: +bias, ReLU, fp16 out.   MODE 1: +bias, LayerNorm, fp32 out.
template <int MODE>
__global__ void k_agg(const uint4* __restrict__ h16, void* __restrict__ outp,
                      const float* __restrict__ bias, const float* __restrict__ gamma,
                      const float* __restrict__ beta, int n0, int n1) {
    int gw = n0 + ((blockIdx.x * blockDim.x + threadIdx.x) >> 5);
    int lane = threadIdx.x & 31;
    if (gw >= n1) return;
    int hw = lane >> 4, sl = lane & 15;
    int s = g_rowptr[gw], e = g_rowptr[gw + 1];
    float di = g_dinv[gw], sw = di * di;

    float acc[8];
    if (hw == 0) {
        uint4 u = h16[gw * 16 + sl];
        const __half2* hp = (const __half2*)&u;
#pragma unroll
        for (int k = 0; k < 4; k++) {
            float2 f = __half22float2(hp[k]);
            acc[2 * k] = f.x * sw;
            acc[2 * k + 1] = f.y * sw;
        }
    } else {
#pragma unroll
        for (int k = 0; k < 8; k++) acc[k] = 0.f;
    }

    int j = s;
    for (; j + 3 < e; j += 4) {
        int2 ea = g_edge[j + hw];
        int2 eb = g_edge[j + 2 + hw];
        uint4 ua = h16[ea.x * 16 + sl];
        uint4 ub = h16[eb.x * 16 + sl];
        float wa = __int_as_float(ea.y), wb = __int_as_float(eb.y);
        const __half2* pa = (const __half2*)&ua;
        const __half2* pb = (const __half2*)&ub;
#pragma unroll
        for (int k = 0; k < 4; k++) {
            float2 fa = __half22float2(pa[k]);
            float2 fb = __half22float2(pb[k]);
            acc[2 * k]     += fa.x * wa + fb.x * wb;
            acc[2 * k + 1] += fa.y * wa + fb.y * wb;
        }
    }
    for (; j < e; j += 2) {
        if (j + hw < e) {
            int2 ea = g_edge[j + hw];
            uint4 ua = h16[ea.x * 16 + sl];
            float wa = __int_as_float(ea.y);
            const __half2* pa = (const __half2*)&ua;
#pragma unroll
            for (int k = 0; k < 4; k++) {
                float2 fa = __half22float2(pa[k]);
                acc[2 * k]     += fa.x * wa;
                acc[2 * k + 1] += fa.y * wa;
            }
        }
    }

#pragma unroll
    for (int k = 0; k < 8; k++)
        acc[k] += __shfl_xor_sync(0xFFFFFFFFu, acc[k], 16);

    float4 bv0 = ((const float4*)bias)[sl * 2];
    float4 bv1 = ((const float4*)bias)[sl * 2 + 1];
    acc[0] += bv0.x; acc[1] += bv0.y; acc[2] += bv0.z; acc[3] += bv0.w;
    acc[4] += bv1.x; acc[5] += bv1.y; acc[6] += bv1.z; acc[7] += bv1.w;

    if (MODE == 0) {
        if (hw == 0) {
            __half2 h[4];
#pragma unroll
            for (int k = 0; k < 4; k++)
                h[k] = __floats2half2_rn(fmaxf(acc[2 * k], 0.f),
                                         fmaxf(acc[2 * k + 1], 0.f));
            ((uint4*)outp)[gw * 16 + sl] = *(uint4*)h;
        }
    } else {
        float sum = 0.f;
#pragma unroll
        for (int k = 0; k < 8; k++) sum += acc[k];
#pragma unroll
        for (int off = 16; off > 0; off >>= 1)
            sum += __shfl_xor_sync(0xFFFFFFFFu, sum, off);
        float mu = sum * (1.0f / 256.0f);   // values duplicated across halves
        float d[8]; float sq = 0.f;
#pragma unroll
        for (int k = 0; k < 8; k++) { d[k] = acc[k] - mu; sq += d[k] * d[k]; }
#pragma unroll
        for (int off = 16; off > 0; off >>= 1)
            sq += __shfl_xor_sync(0xFFFFFFFFu, sq, off);
        float rstd = rsqrtf(sq * (1.0f / 256.0f) + 1e-5f);
        if (hw == 0) {
            float4 g0 = ((const float4*)gamma)[sl * 2];
            float4 g1 = ((const float4*)gamma)[sl * 2 + 1];
            float4 t0 = ((const float4*)beta)[sl * 2];
            float4 t1 = ((const float4*)beta)[sl * 2 + 1];
            float4 o0, o1;
            o0.x = d[0] * rstd * g0.x + t0.x;
            o0.y = d[1] * rstd * g0.y + t0.y;
            o0.z = d[2] * rstd * g0.z + t0.z;
            o0.w = d[3] * rstd * g0.w + t0.w;
            o1.x = d[4] * rstd * g1.x + t1.x;
            o1.y = d[5] * rstd * g1.y + t1.y;
            o1.z = d[6] * rstd * g1.z + t1.z;
            o1.w = d[7] * rstd * g1.w + t1.w;
            ((float4*)outp)[gw * 32 + sl * 2] = o0;
            ((float4*)outp)[gw * 32 + sl * 2 + 1] = o1;
        }
    }
}

// ---------------- launch ----------------
extern "C" void kernel_launch(void* const* d_in, const int* in_sizes, int n_in,
                              void* d_out, int out_size) {
    const float* x   = (const float*)d_in[0];
    const void*  ei  = d_in[1];
    const float* W1  = (const float*)d_in[2];
    const float* b1  = (const float*)d_in[3];
    const float* W2  = (const float*)d_in[4];
    const float* b2  = (const float*)d_in[5];
    const float* gm  = (const float*)d_in[6];
    const float* bt  = (const float*)d_in[7];
    float*       out = (float*)d_out;

    int E = in_sizes[1] / 2;

    __half* h1buf; cudaGetSymbolAddress((void**)&h1buf, g_h1);
    __half* a1buf; cudaGetSymbolAddress((void**)&a1buf, g_a1);
    __half* h2buf; cudaGetSymbolAddress((void**)&h2buf, g_h2);

    const size_t smem_gemm = 2 * 128 * SRS * sizeof(__half);  // 69632 B
    static bool s_init_done = false;
    static cudaStream_t s_side = nullptr;
    static cudaEvent_t ev_fork = nullptr, ev_join = nullptr;
    static cudaEvent_t ev_a = nullptr, ev_g2a = nullptr;
    if (!s_init_done) {
        cudaFuncSetAttribute(k_gemm_tc<false>,
                             cudaFuncAttributeMaxDynamicSharedMemorySize, (int)smem_gemm);
        cudaFuncSetAttribute(k_gemm_tc<true>,
                             cudaFuncAttributeMaxDynamicSharedMemorySize, (int)smem_gemm);
        cudaStreamCreateWithFlags(&s_side, cudaStreamNonBlocking);
        cudaEventCreateWithFlags(&ev_fork, cudaEventDisableTiming);
        cudaEventCreateWithFlags(&ev_join, cudaEventDisableTiming);
        cudaEventCreateWithFlags(&ev_a, cudaEventDisableTiming);
        cudaEventCreateWithFlags(&ev_g2a, cudaEventDisableTiming);
        s_init_done = true;
    }

    int ebl4 = (E / 4 + 255) / 256;
    int ebl = (E + 255) / 256;
    int cnt_blocks = ((E & 3) == 0) ? ebl4 : ebl;
    int gemm_blocks = (NN + 127) / 128;            // 782
    int gemm_a = NHALF / 128;                      // 391
    int gemm_b = gemm_blocks - gemm_a;             // 391
    int aggbl_a = (NHALF * 32 + 255) / 256;
    int aggbl_b = ((NN - NHALF) * 32 + 255) / 256;
    int aggbl_full = (NN * 32 + 255) / 256;

    // ---- fork: gemm1 = x@W1 on side stream (graph-independent) ----
    cudaEventRecord(ev_fork, 0);
    cudaStreamWaitEvent(s_side, ev_fork, 0);
    k_gemm_tc<false><<<gemm_blocks, 256, smem_gemm, s_side>>>(x, W1, h1buf, 0, NN);
    cudaEventRecord(ev_join, s_side);

    // ---- CSR build on main stream ----
    k_count<<<cnt_blocks, 256>>>(ei, E);
    k_reduce<<<NB_SCAN, 256>>>();
    k_scan_final<<<NB_SCAN, 256>>>();
    k_scatter<<<cnt_blocks, 256>>>(ei, E);

    // ---- join gemm1; agg1 split, gemm2_a overlapped with agg1_b ----
    cudaStreamWaitEvent(0, ev_join, 0);
    k_agg<0><<<aggbl_a, 256>>>((const uint4*)h1buf, a1buf, b1, nullptr, nullptr,
                               0, NHALF);
    cudaEventRecord(ev_a, 0);
    cudaStreamWaitEvent(s_side, ev_a, 0);
    k_gemm_tc<true><<<gemm_a, 256, smem_gemm, s_side>>>(a1buf, W2, h2buf, 0, NHALF);
    cudaEventRecord(ev_g2a, s_side);

    k_agg<0><<<aggbl_b, 256>>>((const uint4*)h1buf, a1buf, b1, nullptr, nullptr,
                               NHALF, NN);
    k_gemm_tc<true><<<gemm_b, 256, smem_gemm>>>(a1buf, W2, h2buf, NHALF, NN);
    cudaStreamWaitEvent(0, ev_g2a, 0);

    // ---- agg2 + LayerNorm -> out ----
    k_agg<1><<<aggbl_full, 256>>>((const uint4*)h2buf, out, b2, gm, bt, 0, NN);
}

// round 12
// speedup vs baseline: 1.1535x; 1.0573x over previous
#include <cuda_runtime.h>
#include <cuda_fp16.h>
#include <cuda_bf16.h>
#include <cstdint>

// Problem constants
#define NN 100000
#define EE 1600000
#define DD 128
#define NB_SCAN ((NN + 255) / 256)   // 391 scan blocks

// ---------------- device scratch (no allocations allowed) ----------------
// g_deg/g_done zero on first use (CUDA zero-init), re-zeroed by k_scan_final.
__device__ int    g_done;
__device__ int    g_deg[NN];
__device__ int    g_rowptr[NN + 1];
__device__ int    g_pos[EE];
__device__ int    g_psum[NB_SCAN];
__device__ __align__(16) int2 g_edge[EE];   // (col, wgt-as-int-bits), 16B-aligned
__device__ float  g_dinv[NN];
__device__ __half g_h1[NN * DD];     // GEMM1 output
__device__ __half g_a1[NN * DD];     // layer-1 activation
__device__ __half g_h2[NN * DD];     // GEMM2 output

// ---------------- helpers ----------------
__device__ __forceinline__ int load_idx(const void* ei, int pos, int is64) {
    if (is64) return (int)((const long long*)ei)[pos];
    return ((const int*)ei)[pos];
}

__device__ __forceinline__ int detect_is64(const int* ei32) {
    __shared__ int s_is64;
    if (threadIdx.x == 0) {
        int zeros = 0;
#pragma unroll
        for (int j = 0; j < 64; j++)
            if (ei32[2 * j + 1] == 0) zeros++;
        s_is64 = (zeros >= 60) ? 1 : 0;
    }
    __syncthreads();
    return s_is64;
}

// ---------------- graph-build kernels ----------------

__global__ void k_count(const void* __restrict__ ei, int E) {
    int is64 = detect_is64((const int*)ei);
    int i = blockIdx.x * blockDim.x + threadIdx.x;
    if (!is64 && (E & 3) == 0) {
        int base = 4 * i;
        if (base >= E) return;
        const int4* dst4 = (const int4*)((const int*)ei + E);
        int4 d = dst4[i];
        int4 p = make_int4(0, 0, 0, 0);
        if ((unsigned)d.x < (unsigned)NN) p.x = atomicAdd(&g_deg[d.x], 1);
        if ((unsigned)d.y < (unsigned)NN) p.y = atomicAdd(&g_deg[d.y], 1);
        if ((unsigned)d.z < (unsigned)NN) p.z = atomicAdd(&g_deg[d.z], 1);
        if ((unsigned)d.w < (unsigned)NN) p.w = atomicAdd(&g_deg[d.w], 1);
        ((int4*)g_pos)[i] = p;
    } else {
        if (i >= E) return;
        int d = load_idx(ei, E + i, is64);
        int p = 0;
        if ((unsigned)d < (unsigned)NN) p = atomicAdd(&g_deg[d], 1);
        g_pos[i] = p;
    }
}

// Per-block sums -> g_psum[b]; LAST block scans g_psum (exclusive).
__global__ void k_reduce() {
    __shared__ int ws[8];
    __shared__ int s_last;
    int b = blockIdx.x, t = threadIdx.x;
    int lane = t & 31, w = t >> 5;
    int i = b * 256 + t;
    int v = (i < NN) ? g_deg[i] : 0;
#pragma unroll
    for (int off = 16; off > 0; off >>= 1)
        v += __shfl_xor_sync(0xFFFFFFFFu, v, off);
    if (lane == 0) ws[w] = v;
    __syncthreads();
    if (t == 0) {
        int s = 0;
#pragma unroll
        for (int k = 0; k < 8; k++) s += ws[k];
        g_psum[b] = s;
        __threadfence();
        int done = atomicAdd(&g_done, 1);
        s_last = (done == gridDim.x - 1) ? 1 : 0;
    }
    __syncthreads();
    if (!s_last) return;

    __shared__ int wsum[8];
    __shared__ int carry;
    if (t == 0) carry = 0;
    __syncthreads();
    for (int base = 0; base < NB_SCAN; base += 256) {
        int x = (base + t < NB_SCAN) ? g_psum[base + t] : 0;
        int s = x;
#pragma unroll
        for (int off = 1; off < 32; off <<= 1) {
            int u = __shfl_up_sync(0xFFFFFFFFu, s, off);
            if (lane >= off) s += u;
        }
        if (lane == 31) wsum[w] = s;
        __syncthreads();
        if (w == 0 && lane < 8) {
            int y = wsum[lane];
#pragma unroll
            for (int off = 1; off < 8; off <<= 1) {
                int u = __shfl_up_sync(0xFFu, y, off);
                if (lane >= off) y += u;
            }
            wsum[lane] = y;
        }
        __syncthreads();
        int pre = (w > 0) ? wsum[w - 1] : 0;
        int c = carry;
        if (base + t < NB_SCAN) g_psum[base + t] = c + pre + s - x;
        __syncthreads();
        if (t == 0) carry = c + wsum[7];
        __syncthreads();
    }
}

// Block-local scan + psum offset -> rowptr; dinv fused; re-zero deg/done.
__global__ void k_scan_final() {
    __shared__ int wsum[8];
    int b = blockIdx.x, t = threadIdx.x;
    int lane = t & 31, w = t >> 5;
    int i = b * 256 + t;
    int v = 0;
    if (i < NN) {
        v = g_deg[i];
        g_dinv[i] = rsqrtf((float)v + 1.0f);
        g_deg[i] = 0;
    }
    if (b == 0 && t == 0) g_done = 0;
    int s = v;
#pragma unroll
    for (int off = 1; off < 32; off <<= 1) {
        int u = __shfl_up_sync(0xFFFFFFFFu, s, off);
        if (lane >= off) s += u;
    }
    if (lane == 31) wsum[w] = s;
    __syncthreads();
    if (w == 0 && lane < 8) {
        int ws = wsum[lane];
#pragma unroll
        for (int off = 1; off < 8; off <<= 1) {
            int u = __shfl_up_sync(0xFFu, ws, off);
            if (lane >= off) ws += u;
        }
        wsum[lane] = ws;
    }
    __syncthreads();
    int pre = (w > 0) ? wsum[w - 1] : 0;
    int base = g_psum[b];
    if (i < NN) g_rowptr[i + 1] = base + pre + s;
    if (b == 0 && t == 0) g_rowptr[0] = 0;
}

__device__ __forceinline__ void scatter_one(int s, int d, int p) {
    if ((unsigned)s >= (unsigned)NN || (unsigned)d >= (unsigned)NN) return;
    int idx = g_rowptr[d] + p;
    float w = g_dinv[s] * g_dinv[d];
    g_edge[idx] = make_int2(s, __float_as_int(w));
}

__global__ void k_scatter(const void* __restrict__ ei, int E) {
    int is64 = detect_is64((const int*)ei);
    int i = blockIdx.x * blockDim.x + threadIdx.x;
    if (!is64 && (E & 3) == 0) {
        int base = 4 * i;
        if (base >= E) return;
        const int4* src4 = (const int4*)((const int*)ei);
        const int4* dst4 = (const int4*)((const int*)ei + E);
        int4 s = src4[i];
        int4 d = dst4[i];
        int4 p = ((const int4*)g_pos)[i];
        scatter_one(s.x, d.x, p.x);
        scatter_one(s.y, d.y, p.y);
        scatter_one(s.z, d.z, p.z);
        scatter_one(s.w, d.w, p.w);
    } else {
        if (i >= E) return;
        int s = load_idx(ei, i, is64);
        int d = load_idx(ei, E + i, is64);
        scatter_one(s, d, g_pos[i]);
    }
}

// ---------------- tensor-core GEMM ----------------
#define SRS 136

__device__ __forceinline__ void stage_wt(const float* __restrict__ Wm,
                                         __half* sBT, int tid) {
#pragma unroll
    for (int i = 0; i < 64; i++) {
        int idx = tid + 256 * i;
        int k = idx >> 7, nn = idx & 127;
        sBT[nn * SRS + k] = __float2half(Wm[idx]);
    }
}

__device__ __forceinline__ void gemm_tile(const __half* sA, const __half* sBT,
                                          __half* __restrict__ out, int row0,
                                          int n, int tid) {
    int lane = tid & 31, warp = tid >> 5;
    int g = lane >> 2, tg = lane & 3;
    int rb = warp * 16;

    float acc[16][4];
#pragma unroll
    for (int nt = 0; nt < 16; nt++)
#pragma unroll
        for (int q = 0; q < 4; q++) acc[nt][q] = 0.f;

#pragma unroll
    for (int ks = 0; ks < 8; ks++) {
        int k0 = ks * 16;
        uint32_t a0 = *(const uint32_t*)(sA + (rb + g) * SRS + k0 + tg * 2);
        uint32_t a1 = *(const uint32_t*)(sA + (rb + g + 8) * SRS + k0 + tg * 2);
        uint32_t a2 = *(const uint32_t*)(sA + (rb + g) * SRS + k0 + 8 + tg * 2);
        uint32_t a3 = *(const uint32_t*)(sA + (rb + g + 8) * SRS + k0 + 8 + tg * 2);
#pragma unroll
        for (int nt = 0; nt < 16; nt++) {
            uint32_t b0 = *(const uint32_t*)(sBT + (nt * 8 + g) * SRS + k0 + tg * 2);
            uint32_t b1 = *(const uint32_t*)(sBT + (nt * 8 + g) * SRS + k0 + 8 + tg * 2);
            asm volatile(
                "mma.sync.aligned.m16n8k16.row.col.f32.f16.f16.f32 "
                "{%0,%1,%2,%3},{%4,%5,%6,%7},{%8,%9},{%0,%1,%2,%3};"
                : "+f"(acc[nt][0]), "+f"(acc[nt][1]),
                  "+f"(acc[nt][2]), "+f"(acc[nt][3])
                : "r"(a0), "r"(a1), "r"(a2), "r"(a3), "r"(b0), "r"(b1));
        }
    }

    int r1 = row0 + rb + g;
    int r2 = r1 + 8;
#pragma unroll
    for (int nt = 0; nt < 16; nt++) {
        int c = nt * 8 + tg * 2;
        if (r1 < n) {
            __half2 h = __floats2half2_rn(acc[nt][0], acc[nt][1]);
            *(__half2*)(out + r1 * 128 + c) = h;
        }
        if (r2 < n) {
            __half2 h = __floats2half2_rn(acc[nt][2], acc[nt][3]);
            *(__half2*)(out + r2 * 128 + c) = h;
        }
    }
}

template <bool HALF_IN>
__global__ void k_gemm_tc(const void* __restrict__ Ain, const float* __restrict__ Wm,
                          __half* __restrict__ out, int n) {
    extern __shared__ __half smh[];
    __half* sA = smh;
    __half* sBT = smh + 128 * SRS;
    int tid = threadIdx.x;
    int row0 = blockIdx.x * 128;

    stage_wt(Wm, sBT, tid);

    if (!HALF_IN) {
        const float4* A4 = (const float4*)Ain;
#pragma unroll
        for (int i = 0; i < 16; i++) {
            int idx = tid + 256 * i;
            int r = idx >> 5, c = (idx & 31) * 4;
            float4 v = make_float4(0.f, 0.f, 0.f, 0.f);
            if (row0 + r < n) v = A4[(row0 + r) * 32 + (idx & 31)];
            __half2 h0 = __floats2half2_rn(v.x, v.y);
            __half2 h1 = __floats2half2_rn(v.z, v.w);
            *(__half2*)(sA + r * SRS + c) = h0;
            *(__half2*)(sA + r * SRS + c + 2) = h1;
        }
    } else {
        const uint2* A2 = (const uint2*)Ain;
#pragma unroll
        for (int i = 0; i < 16; i++) {
            int idx = tid + 256 * i;
            int r = idx >> 5, c = (idx & 31) * 4;
            uint2 u = make_uint2(0u, 0u);
            if (row0 + r < n) u = A2[(row0 + r) * 32 + (idx & 31)];
            *(uint32_t*)(sA + r * SRS + c) = u.x;
            *(uint32_t*)(sA + r * SRS + c + 2) = u.y;
        }
    }
    __syncthreads();
    gemm_tile(sA, sBT, out, row0, n, tid);
}

// ---------------- aggregation: warp per node, deep-MLP loop ----------------
// 8 edges per trip: 4 int4 meta loads (2 edges each, warp-broadcast) +
// 8 independent uint2 row loads in flight. Peel to even j for int4 alignment.
__device__ __forceinline__ void fma_edge(float w, uint2 u, float& ax, float& ay,
                                         float& az, float& aw) {
    float2 p0 = __half22float2(*reinterpret_cast<__half2*>(&u.x));
    float2 p1 = __half22float2(*reinterpret_cast<__half2*>(&u.y));
    ax += p0.x * w; ay += p0.y * w; az += p1.x * w; aw += p1.y * w;
}

__device__ __forceinline__ void agg_row(const uint2* __restrict__ hin, int node,
                                        int lane, float& ax, float& ay,
                                        float& az, float& aw) {
    int j = g_rowptr[node];
    int e = g_rowptr[node + 1];
    float di = g_dinv[node];
    float sw = di * di;
    {
        uint2 u = hin[node * 32 + lane];
        float2 f0 = __half22float2(*reinterpret_cast<__half2*>(&u.x));
        float2 f1 = __half22float2(*reinterpret_cast<__half2*>(&u.y));
        ax = f0.x * sw; ay = f0.y * sw; az = f1.x * sw; aw = f1.y * sw;
    }
    // peel to even j (int4 alignment for meta loads)
    if ((j & 1) && j < e) {
        int2 e0 = g_edge[j];
        fma_edge(__int_as_float(e0.y), hin[e0.x * 32 + lane], ax, ay, az, aw);
        j++;
    }
    for (; j + 7 < e; j += 8) {
        int4 m0 = *(const int4*)&g_edge[j];
        int4 m1 = *(const int4*)&g_edge[j + 2];
        int4 m2 = *(const int4*)&g_edge[j + 4];
        int4 m3 = *(const int4*)&g_edge[j + 6];
        uint2 u0 = hin[m0.x * 32 + lane];
        uint2 u1 = hin[m0.z * 32 + lane];
        uint2 u2 = hin[m1.x * 32 + lane];
        uint2 u3 = hin[m1.z * 32 + lane];
        uint2 u4 = hin[m2.x * 32 + lane];
        uint2 u5 = hin[m2.z * 32 + lane];
        uint2 u6 = hin[m3.x * 32 + lane];
        uint2 u7 = hin[m3.z * 32 + lane];
        fma_edge(__int_as_float(m0.y), u0, ax, ay, az, aw);
        fma_edge(__int_as_float(m0.w), u1, ax, ay, az, aw);
        fma_edge(__int_as_float(m1.y), u2, ax, ay, az, aw);
        fma_edge(__int_as_float(m1.w), u3, ax, ay, az, aw);
        fma_edge(__int_as_float(m2.y), u4, ax, ay, az, aw);
        fma_edge(__int_as_float(m2.w), u5, ax, ay, az, aw);
        fma_edge(__int_as_float(m3.y), u6, ax, ay, az, aw);
        fma_edge(__int_as_float(m3.w), u7, ax, ay, az, aw);
    }
    for (; j + 1 < e; j += 2) {
        int4 m0 = *(const int4*)&g_edge[j];
        uint2 u0 = hin[m0.x * 32 + lane];
        uint2 u1 = hin[m0.z * 32 + lane];
        fma_edge(__int_as_float(m0.y), u0, ax, ay, az, aw);
        fma_edge(__int_as_float(m0.w), u1, ax, ay, az, aw);
    }
    if (j < e) {
        int2 e0 = g_edge[j];
        fma_edge(__int_as_float(e0.y), hin[e0.x * 32 + lane], ax, ay, az, aw);
    }
}

// MODE 0: +bias, ReLU, fp16 out.   MODE 1: +bias, LayerNorm, fp32 out.
template <int MODE>
__global__ void k_agg(const uint2* __restrict__ hin, void* __restrict__ outp,
                      const float* __restrict__ bias, const float* __restrict__ gamma,
                      const float* __restrict__ beta) {
    int gw = (blockIdx.x * blockDim.x + threadIdx.x) >> 5;
    int lane = threadIdx.x & 31;
    if (gw >= NN) return;
    float ax, ay, az, aw;
    agg_row(hin, gw, lane, ax, ay, az, aw);

    float4 bv = ((const float4*)bias)[lane];
    ax += bv.x; ay += bv.y; az += bv.z; aw += bv.w;

    if (MODE == 0) {
        __half2 h0 = __floats2half2_rn(fmaxf(ax, 0.f), fmaxf(ay, 0.f));
        __half2 h1 = __floats2half2_rn(fmaxf(az, 0.f), fmaxf(aw, 0.f));
        uint2 u;
        u.x = *reinterpret_cast<unsigned*>(&h0);
        u.y = *reinterpret_cast<unsigned*>(&h1);
        ((uint2*)outp)[gw * 32 + lane] = u;
    } else {
        float sum = ax + ay + az + aw;
#pragma unroll
        for (int off = 16; off > 0; off >>= 1)
            sum += __shfl_xor_sync(0xFFFFFFFFu, sum, off);
        float mu = sum * (1.0f / 128.0f);
        float dx = ax - mu, dy = ay - mu, dz = az - mu, dw = aw - mu;
        float sq = dx * dx + dy * dy + dz * dz + dw * dw;
#pragma unroll
        for (int off = 16; off > 0; off >>= 1)
            sq += __shfl_xor_sync(0xFFFFFFFFu, sq, off);
        float rstd = rsqrtf(sq * (1.0f / 128.0f) + 1e-5f);
        float4 gv = ((const float4*)gamma)[lane];
        float4 btv = ((const float4*)beta)[lane];
        float4 o;
        o.x = dx * rstd * gv.x + btv.x;
        o.y = dy * rstd * gv.y + btv.y;
        o.z = dz * rstd * gv.z + btv.z;
        o.w = dw * rstd * gv.w + btv.w;
        ((float4*)outp)[gw * 32 + lane] = o;
    }
}

// ---------------- launch ----------------
extern "C" void kernel_launch(void* const* d_in, const int* in_sizes, int n_in,
                              void* d_out, int out_size) {
    const float* x   = (const float*)d_in[0];
    const void*  ei  = d_in[1];
    const float* W1  = (const float*)d_in[2];
    const float* b1  = (const float*)d_in[3];
    const float* W2  = (const float*)d_in[4];
    const float* b2  = (const float*)d_in[5];
    const float* gm  = (const float*)d_in[6];
    const float* bt  = (const float*)d_in[7];
    float*       out = (float*)d_out;

    int E = in_sizes[1] / 2;

    __half* h1buf; cudaGetSymbolAddress((void**)&h1buf, g_h1);
    __half* a1buf; cudaGetSymbolAddress((void**)&a1buf, g_a1);
    __half* h2buf; cudaGetSymbolAddress((void**)&h2buf, g_h2);

    const size_t smem_gemm = 2 * 128 * SRS * sizeof(__half);  // 69632 B
    static bool s_init_done = false;
    static cudaStream_t s_side = nullptr;
    static cudaEvent_t ev_fork = nullptr, ev_join = nullptr;
    if (!s_init_done) {
        cudaFuncSetAttribute(k_gemm_tc<false>,
                             cudaFuncAttributeMaxDynamicSharedMemorySize, (int)smem_gemm);
        cudaFuncSetAttribute(k_gemm_tc<true>,
                             cudaFuncAttributeMaxDynamicSharedMemorySize, (int)smem_gemm);
        cudaStreamCreateWithFlags(&s_side, cudaStreamNonBlocking);
        cudaEventCreateWithFlags(&ev_fork, cudaEventDisableTiming);
        cudaEventCreateWithFlags(&ev_join, cudaEventDisableTiming);
        s_init_done = true;
    }

    int ebl4 = (E / 4 + 255) / 256;
    int ebl = (E + 255) / 256;
    int cnt_blocks = ((E & 3) == 0) ? ebl4 : ebl;
    int agg_blocks = (NN * 32 + 255) / 256;
    int gemm_blocks = (NN + 127) / 128;

    // ---- fork: gemm1 = x@W1 on side stream (graph-independent) ----
    cudaEventRecord(ev_fork, 0);
    cudaStreamWaitEvent(s_side, ev_fork, 0);
    k_gemm_tc<false><<<gemm_blocks, 256, smem_gemm, s_side>>>(x, W1, h1buf, NN);
    cudaEventRecord(ev_join, s_side);

    // ---- CSR build on main stream (deg/done pre-zeroed invariant) ----
    k_count<<<cnt_blocks, 256>>>(ei, E);
    k_reduce<<<NB_SCAN, 256>>>();
    k_scan_final<<<NB_SCAN, 256>>>();
    k_scatter<<<cnt_blocks, 256>>>(ei, E);

    // ---- join gemm1, then agg1 -> a1 ----
    cudaStreamWaitEvent(0, ev_join, 0);
    k_agg<0><<<agg_blocks, 256>>>((const uint2*)h1buf, a1buf, b1, nullptr, nullptr);

    // ---- gemm2: h2 = a1@W2 ----
    k_gemm_tc<true><<<gemm_blocks, 256, smem_gemm>>>(a1buf, W2, h2buf, NN);

    // ---- agg2 + LayerNorm -> out ----
    k_agg<1><<<agg_blocks, 256>>>((const uint2*)h2buf, out, b2, gm, bt);
}

// round 13
// speedup vs baseline: 1.2453x; 1.0796x over previous
#include <cuda_runtime.h>
#include <cuda_fp16.h>
#include <cuda_bf16.h>
#include <cstdint>

// Problem constants
#define NN 100000
#define EE 1600000
#define DD 128
#define NB_SCAN ((NN + 255) / 256)   // 391 scan blocks

// ---------------- device scratch (no allocations allowed) ----------------
// g_deg/g_done zero on first use (CUDA zero-init), re-zeroed by k_scan_final.
__device__ int    g_done;
__device__ int    g_deg[NN];
__device__ int    g_rowptr[NN + 1];
__device__ int    g_cursor[NN];
__device__ int    g_psum[NB_SCAN];
__device__ __align__(16) int2 g_edge[EE];   // (col, dinv[col]-as-int-bits)
__device__ float  g_dinv[NN];
__device__ __half g_h1[NN * DD];     // GEMM1 output
__device__ __half g_a1[NN * DD];     // layer-1 activation
__device__ __half g_h2[NN * DD];     // GEMM2 output

// ---------------- helpers ----------------
__device__ __forceinline__ int load_idx(const void* ei, int pos, int is64) {
    if (is64) return (int)((const long long*)ei)[pos];
    return ((const int*)ei)[pos];
}

__device__ __forceinline__ int detect_is64(const int* ei32) {
    __shared__ int s_is64;
    if (threadIdx.x == 0) {
        int zeros = 0;
#pragma unroll
        for (int j = 0; j < 64; j++)
            if (ei32[2 * j + 1] == 0) zeros++;
        s_is64 = (zeros >= 60) ? 1 : 0;
    }
    __syncthreads();
    return s_is64;
}

// ---------------- graph-build kernels ----------------

// count degrees; return value unused -> REDG (no scoreboard wait).
__global__ void k_count(const void* __restrict__ ei, int E) {
    int is64 = detect_is64((const int*)ei);
    int i = blockIdx.x * blockDim.x + threadIdx.x;
    if (!is64 && (E & 3) == 0) {
        int base = 4 * i;
        if (base >= E) return;
        const int4* dst4 = (const int4*)((const int*)ei + E);
        int4 d = dst4[i];
        if ((unsigned)d.x < (unsigned)NN) atomicAdd(&g_deg[d.x], 1);
        if ((unsigned)d.y < (unsigned)NN) atomicAdd(&g_deg[d.y], 1);
        if ((unsigned)d.z < (unsigned)NN) atomicAdd(&g_deg[d.z], 1);
        if ((unsigned)d.w < (unsigned)NN) atomicAdd(&g_deg[d.w], 1);
    } else {
        if (i >= E) return;
        int d = load_idx(ei, E + i, is64);
        if ((unsigned)d < (unsigned)NN) atomicAdd(&g_deg[d], 1);
    }
}

// Per-block sums -> g_psum[b]; LAST block scans g_psum (exclusive).
__global__ void k_reduce() {
    __shared__ int ws[8];
    __shared__ int s_last;
    int b = blockIdx.x, t = threadIdx.x;
    int lane = t & 31, w = t >> 5;
    int i = b * 256 + t;
    int v = (i < NN) ? g_deg[i] : 0;
#pragma unroll
    for (int off = 16; off > 0; off >>= 1)
        v += __shfl_xor_sync(0xFFFFFFFFu, v, off);
    if (lane == 0) ws[w] = v;
    __syncthreads();
    if (t == 0) {
        int s = 0;
#pragma unroll
        for (int k = 0; k < 8; k++) s += ws[k];
        g_psum[b] = s;
        __threadfence();
        int done = atomicAdd(&g_done, 1);
        s_last = (done == gridDim.x - 1) ? 1 : 0;
    }
    __syncthreads();
    if (!s_last) return;

    __shared__ int wsum[8];
    __shared__ int carry;
    if (t == 0) carry = 0;
    __syncthreads();
    for (int base = 0; base < NB_SCAN; base += 256) {
        int x = (base + t < NB_SCAN) ? g_psum[base + t] : 0;
        int s = x;
#pragma unroll
        for (int off = 1; off < 32; off <<= 1) {
            int u = __shfl_up_sync(0xFFFFFFFFu, s, off);
            if (lane >= off) s += u;
        }
        if (lane == 31) wsum[w] = s;
        __syncthreads();
        if (w == 0 && lane < 8) {
            int y = wsum[lane];
#pragma unroll
            for (int off = 1; off < 8; off <<= 1) {
                int u = __shfl_up_sync(0xFFu, y, off);
                if (lane >= off) y += u;
            }
            wsum[lane] = y;
        }
        __syncthreads();
        int pre = (w > 0) ? wsum[w - 1] : 0;
        int c = carry;
        if (base + t < NB_SCAN) g_psum[base + t] = c + pre + s - x;
        __syncthreads();
        if (t == 0) carry = c + wsum[7];
        __syncthreads();
    }
}

// Block-local scan + psum offset -> rowptr AND cursor (= row start);
// dinv fused; re-zero deg/done for next call.
__global__ void k_scan_final() {
    __shared__ int wsum[8];
    int b = blockIdx.x, t = threadIdx.x;
    int lane = t & 31, w = t >> 5;
    int i = b * 256 + t;
    int v = 0;
    if (i < NN) {
        v = g_deg[i];
        g_dinv[i] = rsqrtf((float)v + 1.0f);
        g_deg[i] = 0;
    }
    if (b == 0 && t == 0) g_done = 0;
    int s = v;
#pragma unroll
    for (int off = 1; off < 32; off <<= 1) {
        int u = __shfl_up_sync(0xFFFFFFFFu, s, off);
        if (lane >= off) s += u;
    }
    if (lane == 31) wsum[w] = s;
    __syncthreads();
    if (w == 0 && lane < 8) {
        int ws = wsum[lane];
#pragma unroll
        for (int off = 1; off < 8; off <<= 1) {
            int u = __shfl_up_sync(0xFFu, ws, off);
            if (lane >= off) ws += u;
        }
        wsum[lane] = ws;
    }
    __syncthreads();
    int pre = (w > 0) ? wsum[w - 1] : 0;
    int base = g_psum[b];
    if (i < NN) {
        g_rowptr[i + 1] = base + pre + s;
        g_cursor[i] = base + pre + s - v;   // exclusive start of row i
    }
    if (b == 0 && t == 0) g_rowptr[0] = 0;
}

// cursor-based scatter: one random atomic + one random gather per edge.
__device__ __forceinline__ void scatter_one(int s, int d) {
    if ((unsigned)s >= (unsigned)NN || (unsigned)d >= (unsigned)NN) return;
    int idx = atomicAdd(&g_cursor[d], 1);
    g_edge[idx] = make_int2(s, __float_as_int(g_dinv[s]));
}

__global__ void k_scatter(const void* __restrict__ ei, int E) {
    int is64 = detect_is64((const int*)ei);
    int i = blockIdx.x * blockDim.x + threadIdx.x;
    if (!is64 && (E & 3) == 0) {
        int base = 4 * i;
        if (base >= E) return;
        const int4* src4 = (const int4*)((const int*)ei);
        const int4* dst4 = (const int4*)((const int*)ei + E);
        int4 s = src4[i];
        int4 d = dst4[i];
        scatter_one(s.x, d.x);
        scatter_one(s.y, d.y);
        scatter_one(s.z, d.z);
        scatter_one(s.w, d.w);
    } else {
        if (i >= E) return;
        int s = load_idx(ei, i, is64);
        int d = load_idx(ei, E + i, is64);
        scatter_one(s, d);
    }
}

// ---------------- tensor-core GEMM ----------------
#define SRS 136

__device__ __forceinline__ void stage_wt(const float* __restrict__ Wm,
                                         __half* sBT, int tid) {
#pragma unroll
    for (int i = 0; i < 64; i++) {
        int idx = tid + 256 * i;
        int k = idx >> 7, nn = idx & 127;
        sBT[nn * SRS + k] = __float2half(Wm[idx]);
    }
}

__device__ __forceinline__ void gemm_tile(const __half* sA, const __half* sBT,
                                          __half* __restrict__ out, int row0,
                                          int n, int tid) {
    int lane = tid & 31, warp = tid >> 5;
    int g = lane >> 2, tg = lane & 3;
    int rb = warp * 16;

    float acc[16][4];
#pragma unroll
    for (int nt = 0; nt < 16; nt++)
#pragma unroll
        for (int q = 0; q < 4; q++) acc[nt][q] = 0.f;

#pragma unroll
    for (int ks = 0; ks < 8; ks++) {
        int k0 = ks * 16;
        uint32_t a0 = *(const uint32_t*)(sA + (rb + g) * SRS + k0 + tg * 2);
        uint32_t a1 = *(const uint32_t*)(sA + (rb + g + 8) * SRS + k0 + tg * 2);
        uint32_t a2 = *(const uint32_t*)(sA + (rb + g) * SRS + k0 + 8 + tg * 2);
        uint32_t a3 = *(const uint32_t*)(sA + (rb + g + 8) * SRS + k0 + 8 + tg * 2);
#pragma unroll
        for (int nt = 0; nt < 16; nt++) {
            uint32_t b0 = *(const uint32_t*)(sBT + (nt * 8 + g) * SRS + k0 + tg * 2);
            uint32_t b1 = *(const uint32_t*)(sBT + (nt * 8 + g) * SRS + k0 + 8 + tg * 2);
            asm volatile(
                "mma.sync.aligned.m16n8k16.row.col.f32.f16.f16.f32 "
                "{%0,%1,%2,%3},{%4,%5,%6,%7},{%8,%9},{%0,%1,%2,%3};"
                : "+f"(acc[nt][0]), "+f"(acc[nt][1]),
                  "+f"(acc[nt][2]), "+f"(acc[nt][3])
                : "r"(a0), "r"(a1), "r"(a2), "r"(a3), "r"(b0), "r"(b1));
        }
    }

    int r1 = row0 + rb + g;
    int r2 = r1 + 8;
#pragma unroll
    for (int nt = 0; nt < 16; nt++) {
        int c = nt * 8 + tg * 2;
        if (r1 < n) {
            __half2 h = __floats2half2_rn(acc[nt][0], acc[nt][1]);
            *(__half2*)(out + r1 * 128 + c) = h;
        }
        if (r2 < n) {
            __half2 h = __floats2half2_rn(acc[nt][2], acc[nt][3]);
            *(__half2*)(out + r2 * 128 + c) = h;
        }
    }
}

template <bool HALF_IN>
__global__ void k_gemm_tc(const void* __restrict__ Ain, const float* __restrict__ Wm,
                          __half* __restrict__ out, int n) {
    extern __shared__ __half smh[];
    __half* sA = smh;
    __half* sBT = smh + 128 * SRS;
    int tid = threadIdx.x;
    int row0 = blockIdx.x * 128;

    stage_wt(Wm, sBT, tid);

    if (!HALF_IN) {
        const float4* A4 = (const float4*)Ain;
#pragma unroll
        for (int i = 0; i < 16; i++) {
            int idx = tid + 256 * i;
            int r = idx >> 5, c = (idx & 31) * 4;
            float4 v = make_float4(0.f, 0.f, 0.f, 0.f);
            if (row0 + r < n) v = A4[(row0 + r) * 32 + (idx & 31)];
            __half2 h0 = __floats2half2_rn(v.x, v.y);
            __half2 h1 = __floats2half2_rn(v.z, v.w);
            *(__half2*)(sA + r * SRS + c) = h0;
            *(__half2*)(sA + r * SRS + c + 2) = h1;
        }
    } else {
        const uint2* A2 = (const uint2*)Ain;
#pragma unroll
        for (int i = 0; i < 16; i++) {
            int idx = tid + 256 * i;
            int r = idx >> 5, c = (idx & 31) * 4;
            uint2 u = make_uint2(0u, 0u);
            if (row0 + r < n) u = A2[(row0 + r) * 32 + (idx & 31)];
            *(uint32_t*)(sA + r * SRS + c) = u.x;
            *(uint32_t*)(sA + r * SRS + c + 2) = u.y;
        }
    }
    __syncthreads();
    gemm_tile(sA, sBT, out, row0, n, tid);
}

// ---------------- aggregation: warp per node, deep-MLP loop ----------------
// Factored norm: edge weight = dinv[src]; final scale by dinv[node]:
// out = dinv[d] * ( sum_j dinv[s_j] h[s_j] + dinv[d] h[d] )
__device__ __forceinline__ void fma_edge(float w, uint2 u, float& ax, float& ay,
                                         float& az, float& aw) {
    float2 p0 = __half22float2(*reinterpret_cast<__half2*>(&u.x));
    float2 p1 = __half22float2(*reinterpret_cast<__half2*>(&u.y));
    ax += p0.x * w; ay += p0.y * w; az += p1.x * w; aw += p1.y * w;
}

__device__ __forceinline__ void agg_row(const uint2* __restrict__ hin, int node,
                                        int lane, float& ax, float& ay,
                                        float& az, float& aw) {
    int j = g_rowptr[node];
    int e = g_rowptr[node + 1];
    float di = g_dinv[node];
    {
        uint2 u = hin[node * 32 + lane];
        float2 f0 = __half22float2(*reinterpret_cast<__half2*>(&u.x));
        float2 f1 = __half22float2(*reinterpret_cast<__half2*>(&u.y));
        ax = f0.x * di; ay = f0.y * di; az = f1.x * di; aw = f1.y * di;
    }
    if ((j & 1) && j < e) {
        int2 e0 = g_edge[j];
        fma_edge(__int_as_float(e0.y), hin[e0.x * 32 + lane], ax, ay, az, aw);
        j++;
    }
    for (; j + 7 < e; j += 8) {
        int4 m0 = *(const int4*)&g_edge[j];
        int4 m1 = *(const int4*)&g_edge[j + 2];
        int4 m2 = *(const int4*)&g_edge[j + 4];
        int4 m3 = *(const int4*)&g_edge[j + 6];
        uint2 u0 = hin[m0.x * 32 + lane];
        uint2 u1 = hin[m0.z * 32 + lane];
        uint2 u2 = hin[m1.x * 32 + lane];
        uint2 u3 = hin[m1.z * 32 + lane];
        uint2 u4 = hin[m2.x * 32 + lane];
        uint2 u5 = hin[m2.z * 32 + lane];
        uint2 u6 = hin[m3.x * 32 + lane];
        uint2 u7 = hin[m3.z * 32 + lane];
        fma_edge(__int_as_float(m0.y), u0, ax, ay, az, aw);
        fma_edge(__int_as_float(m0.w), u1, ax, ay, az, aw);
        fma_edge(__int_as_float(m1.y), u2, ax, ay, az, aw);
        fma_edge(__int_as_float(m1.w), u3, ax, ay, az, aw);
        fma_edge(__int_as_float(m2.y), u4, ax, ay, az, aw);
        fma_edge(__int_as_float(m2.w), u5, ax, ay, az, aw);
        fma_edge(__int_as_float(m3.y), u6, ax, ay, az, aw);
        fma_edge(__int_as_float(m3.w), u7, ax, ay, az, aw);
    }
    for (; j + 1 < e; j += 2) {
        int4 m0 = *(const int4*)&g_edge[j];
        uint2 u0 = hin[m0.x * 32 + lane];
        uint2 u1 = hin[m0.z * 32 + lane];
        fma_edge(__int_as_float(m0.y), u0, ax, ay, az, aw);
        fma_edge(__int_as_float(m0.w), u1, ax, ay, az, aw);
    }
    if (j < e) {
        int2 e0 = g_edge[j];
        fma_edge(__int_as_float(e0.y), hin[e0.x * 32 + lane], ax, ay, az, aw);
    }
    ax *= di; ay *= di; az *= di; aw *= di;
}

// MODE 0: +bias, ReLU, fp16 out.   MODE 1: +bias, LayerNorm, fp32 out.
template <int MODE>
__global__ void k_agg(const uint2* __restrict__ hin, void* __restrict__ outp,
                      const float* __restrict__ bias, const float* __restrict__ gamma,
                      const float* __restrict__ beta) {
    int gw = (blockIdx.x * blockDim.x + threadIdx.x) >> 5;
    int lane = threadIdx.x & 31;
    if (gw >= NN) return;
    float ax, ay, az, aw;
    agg_row(hin, gw, lane, ax, ay, az, aw);

    float4 bv = ((const float4*)bias)[lane];
    ax += bv.x; ay += bv.y; az += bv.z; aw += bv.w;

    if (MODE == 0) {
        __half2 h0 = __floats2half2_rn(fmaxf(ax, 0.f), fmaxf(ay, 0.f));
        __half2 h1 = __floats2half2_rn(fmaxf(az, 0.f), fmaxf(aw, 0.f));
        uint2 u;
        u.x = *reinterpret_cast<unsigned*>(&h0);
        u.y = *reinterpret_cast<unsigned*>(&h1);
        ((uint2*)outp)[gw * 32 + lane] = u;
    } else {
        float sum = ax + ay + az + aw;
#pragma unroll
        for (int off = 16; off > 0; off >>= 1)
            sum += __shfl_xor_sync(0xFFFFFFFFu, sum, off);
        float mu = sum * (1.0f / 128.0f);
        float dx = ax - mu, dy = ay - mu, dz = az - mu, dw = aw - mu;
        float sq = dx * dx + dy * dy + dz * dz + dw * dw;
#pragma unroll
        for (int off = 16; off > 0; off >>= 1)
            sq += __shfl_xor_sync(0xFFFFFFFFu, sq, off);
        float rstd = rsqrtf(sq * (1.0f / 128.0f) + 1e-5f);
        float4 gv = ((const float4*)gamma)[lane];
        float4 btv = ((const float4*)beta)[lane];
        float4 o;
        o.x = dx * rstd * gv.x + btv.x;
        o.y = dy * rstd * gv.y + btv.y;
        o.z = dz * rstd * gv.z + btv.z;
        o.w = dw * rstd * gv.w + btv.w;
        ((float4*)outp)[gw * 32 + lane] = o;
    }
}

// ---------------- launch ----------------
extern "C" void kernel_launch(void* const* d_in, const int* in_sizes, int n_in,
                              void* d_out, int out_size) {
    const float* x   = (const float*)d_in[0];
    const void*  ei  = d_in[1];
    const float* W1  = (const float*)d_in[2];
    const float* b1  = (const float*)d_in[3];
    const float* W2  = (const float*)d_in[4];
    const float* b2  = (const float*)d_in[5];
    const float* gm  = (const float*)d_in[6];
    const float* bt  = (const float*)d_in[7];
    float*       out = (float*)d_out;

    int E = in_sizes[1] / 2;

    __half* h1buf; cudaGetSymbolAddress((void**)&h1buf, g_h1);
    __half* a1buf; cudaGetSymbolAddress((void**)&a1buf, g_a1);
    __half* h2buf; cudaGetSymbolAddress((void**)&h2buf, g_h2);

    const size_t smem_gemm = 2 * 128 * SRS * sizeof(__half);  // 69632 B
    static bool s_init_done = false;
    static cudaStream_t s_side = nullptr;
    static cudaEvent_t ev_fork = nullptr, ev_join = nullptr;
    if (!s_init_done) {
        cudaFuncSetAttribute(k_gemm_tc<false>,
                             cudaFuncAttributeMaxDynamicSharedMemorySize, (int)smem_gemm);
        cudaFuncSetAttribute(k_gemm_tc<true>,
                             cudaFuncAttributeMaxDynamicSharedMemorySize, (int)smem_gemm);
        cudaStreamCreateWithFlags(&s_side, cudaStreamNonBlocking);
        cudaEventCreateWithFlags(&ev_fork, cudaEventDisableTiming);
        cudaEventCreateWithFlags(&ev_join, cudaEventDisableTiming);
        s_init_done = true;
    }

    int ebl4 = (E / 4 + 255) / 256;
    int ebl = (E + 255) / 256;
    int cnt_blocks = ((E & 3) == 0) ? ebl4 : ebl;
    int agg_blocks = (NN * 32 + 255) / 256;
    int gemm_blocks = (NN + 127) / 128;

    // ---- fork: gemm1 = x@W1 on side stream (graph-independent) ----
    cudaEventRecord(ev_fork, 0);
    cudaStreamWaitEvent(s_side, ev_fork, 0);
    k_gemm_tc<false><<<gemm_blocks, 256, smem_gemm, s_side>>>(x, W1, h1buf, NN);
    cudaEventRecord(ev_join, s_side);

    // ---- CSR build on main stream (deg/done pre-zeroed invariant) ----
    k_count<<<cnt_blocks, 256>>>(ei, E);
    k_reduce<<<NB_SCAN, 256>>>();
    k_scan_final<<<NB_SCAN, 256>>>();
    k_scatter<<<cnt_blocks, 256>>>(ei, E);

    // ---- join gemm1, then agg1 -> a1 ----
    cudaStreamWaitEvent(0, ev_join, 0);
    k_agg<0><<<agg_blocks, 256>>>((const uint2*)h1buf, a1buf, b1, nullptr, nullptr);

    // ---- gemm2: h2 = a1@W2 ----
    k_gemm_tc<true><<<gemm_blocks, 256, smem_gemm>>>(a1buf, W2, h2buf, NN);

    // ---- agg2 + LayerNorm -> out ----
    k_agg<1><<<agg_blocks, 256>>>((const uint2*)h2buf, out, b2, gm, bt);
}